// round 13
// baseline (speedup 1.0000x reference)
#include <cuda_runtime.h>
#include <cstddef>

#define TT 9
#define SS 9
#define FF 512
#define H1 32
#define H2 64
#define XROW 1032          // floats per s-pair row (2*FF + 8 pad)
#define BASE7 7.0f

typedef unsigned long long ull;

// ---------------- device scratch ----------------
__device__ float g_W1p [TT * 8 * 16 * 32 * 4];   // rotated W1: [t][w8][g16][lane32][c4]
                                                 // lane=(fh<<4|op), c=(df<<1|do)
                                                 // f = w*64+g*4+fh*2+df, o = op*2+do
__device__ float g_W2r [TT * H1];
__device__ float g_mW1b[16 * 16 * 32 * 4];       // rotated mW1: [quad16][step16][lane32]float4
__device__ float g_mW2r[H2];
__device__ float g_team[4096 * TT * FF];
__device__ float g_tq  [4096 * TT];
__device__ float g_sink;

// ---------------- profiling-alignment dummies (ncu capture lands on k1) ----------------
__global__ void kalign() {
    if (threadIdx.x == 0xFFFFFFFFu) g_sink = 0.0f;
}

// ---------------- f32x2 helpers ----------------
__device__ __forceinline__ ull ffma2(ull a, ull b, ull c) {
    ull d;
    asm("fma.rn.f32x2 %0, %1, %2, %3;" : "=l"(d) : "l"(a), "l"(b), "l"(c));
    return d;
}
__device__ __forceinline__ ull fadd2(ull a, ull b) {
    ull d;
    asm("add.rn.f32x2 %0, %1, %2;" : "=l"(d) : "l"(a), "l"(b));
    return d;
}
__device__ __forceinline__ ull dup2(float x) {
    ull r;
    asm("mov.b64 %0, {%1, %1};" : "=l"(r) : "f"(x));
    return r;
}
__device__ __forceinline__ float2 u2f(ull r) {
    float2 v;
    asm("mov.b64 {%0, %1}, %2;" : "=f"(v.x), "=f"(v.y) : "l"(r));
    return v;
}

__device__ __forceinline__ float pnorm1(float h, float g, float b) {
    float m = h - BASE7 * floorf(h * (1.0f / BASE7));
    return g * ((m - 3.5f) * (1.0f / 3.5f)) + b;
}

// rotate-absorb: coeff of x_f in dot(rot(x), Wrow)
__device__ __forceinline__ float rotv(const float* __restrict__ Wrow,
                                      const float* __restrict__ ang,
                                      int f, int nplanes) {
    if (f >= 2 * nplanes) return Wrow[f];
    int p = f >> 1; float a = ang[p];
    float c = cosf(a), s = sinf(a);
    float w0 = Wrow[2 * p], w1 = Wrow[2 * p + 1];
    return (f & 1) ? (c * w1 - s * w0) : (c * w0 + s * w1);
}

// ---------------- prep: rotate + re-tile weights ----------------
__global__ void kprep(const float* __restrict__ W1, const float* __restrict__ ang1,
                      const float* __restrict__ W2, const float* __restrict__ ang2,
                      const float* __restrict__ mW1, const float* __restrict__ mang1,
                      const float* __restrict__ mW2, const float* __restrict__ mang2)
{
    int idx = blockIdx.x * 256 + threadIdx.x;
    const int N1 = TT * 16384;     // g_W1p
    const int N2 = TT * H1;        // g_W2r
    const int N3 = 32768;          // g_mW1b
    const int N4 = H2;             // g_mW2r
    if (idx < N1) {
        int c    =  idx        & 3;
        int lane = (idx >> 2)  & 31;
        int g    = (idx >> 7)  & 15;
        int w    = (idx >> 11) & 7;
        int t    =  idx >> 14;
        int op = lane & 15, fh = lane >> 4;
        int df = c >> 1, dd = c & 1;
        int f = w * 64 + g * 4 + fh * 2 + df;
        int o = op * 2 + dd;
        g_W1p[idx] = rotv(W1 + ((size_t)t * H1 + o) * FF, ang1 + 2 * t, f, 2);
    } else if (idx < N1 + N2) {
        int jj = idx - N1; int t = jj / H1, o = jj - t * H1;
        g_W2r[jj] = rotv(W2 + t * H1, ang2 + 2 * t, o, 2);
    } else if (idx < N1 + N2 + N3) {
        int jj = idx - N1 - N2;
        int c    =  jj        & 3;
        int lane = (jj >> 2)  & 31;
        int step = (jj >> 7)  & 15;
        int q    = (jj >> 11) & 15;
        int o = 4 * q + c;
        int f = 32 * step + lane;
        g_mW1b[jj] = rotv(mW1 + (size_t)o * FF, mang1, f, 4);
    } else if (idx < N1 + N2 + N3 + N4) {
        int o = idx - N1 - N2 - N3;
        g_mW2r[o] = rotv(mW2, mang2, o, 2);
    }
}

// ---------------- kernel 1: per (t, b-pair) — weights amortized over 2 batches ----------------
__global__ __launch_bounds__(256, 4) void k1(const float* __restrict__ path,
                                             const float* __restrict__ b1,
                                             const float* __restrict__ gamma1,
                                             const float* __restrict__ beta1)
{
    __shared__ float xsp[2][4 * XROW];       // per-batch s-pair rows
    __shared__ float xs8[2][FF + 8];         // per-batch s=8 row
    __shared__ float psA[8 * 4 * 32 * 2];    // warp partials: [w][sp][o]{lo,hi} (reused per bi)
    __shared__ float ps8[8 * 32];            // warp partials s=8
    __shared__ float scp[SS * 33];           // score partials
    __shared__ float qsm[16];

    const int t = blockIdx.x;
    const int b0 = 2 * blockIdx.y;
    const int tid = threadIdx.x, lane = tid & 31, w = tid >> 5;
    const int op = lane & 15, fh = lane >> 4;

    // stage x for both batches (incremental f,s walker)
    #pragma unroll
    for (int bi = 0; bi < 2; ++bi) {
        const float* xb = path + (size_t)(b0 + bi) * (FF * TT * SS) + t * SS;
        int f = tid / 9;
        int s = tid - f * 9;
        const float* p = xb + f * (TT * SS) + s;
        #pragma unroll
        for (int it = 0; it < 18; ++it) {
            float v = *p;
            if (s == 8) xs8[bi][f] = v;
            else xsp[bi][(s >> 1) * XROW + 2 * f + (s & 1)] = v;
            s += 4; f += 28;
            if (s >= 9) { s -= 9; f += 1; p += 29 * (TT * SS) - 5; }
            else        {                p += 28 * (TT * SS) + 4; }
        }
    }
    __syncthreads();

    // mainloop: lane owns o-pair {2op,2op+1}; warp w covers f in [64w,64w+64);
    // each weight float4 loaded ONCE, applied to both batches.
    ull A00 = 0, A01 = 0, A02 = 0, A03 = 0, A10 = 0, A11 = 0, A12 = 0, A13 = 0;
    ull B00 = 0, B01 = 0, B02 = 0, B03 = 0, B10 = 0, B11 = 0, B12 = 0, B13 = 0;
    float A80 = 0.f, A81 = 0.f, B80 = 0.f, B81 = 0.f;

    const float4* wq = reinterpret_cast<const float4*>(g_W1p)
                     + ((size_t)(t * 8 + w) * 16) * 32 + lane;
    const float* xA0 = &xsp[0][2 * (w * 64 + 2 * fh)];
    const float* xB0 = &xsp[1][2 * (w * 64 + 2 * fh)];
    const float* x8A = &xs8[0][w * 64 + 2 * fh];
    const float* x8B = &xs8[1][w * 64 + 2 * fh];

    #pragma unroll
    for (int g = 0; g < 16; ++g) {
        float4 wv = wq[g * 32];
        const float* xgA = xA0 + 8 * g;
        const float* xgB = xB0 + 8 * g;
        ulonglong2 rA0 = *reinterpret_cast<const ulonglong2*>(xgA + 0 * XROW);
        ulonglong2 rA1 = *reinterpret_cast<const ulonglong2*>(xgA + 1 * XROW);
        ulonglong2 rA2 = *reinterpret_cast<const ulonglong2*>(xgA + 2 * XROW);
        ulonglong2 rA3 = *reinterpret_cast<const ulonglong2*>(xgA + 3 * XROW);
        ulonglong2 rB0 = *reinterpret_cast<const ulonglong2*>(xgB + 0 * XROW);
        ulonglong2 rB1 = *reinterpret_cast<const ulonglong2*>(xgB + 1 * XROW);
        ulonglong2 rB2 = *reinterpret_cast<const ulonglong2*>(xgB + 2 * XROW);
        ulonglong2 rB3 = *reinterpret_cast<const ulonglong2*>(xgB + 3 * XROW);
        float2 x8a = *reinterpret_cast<const float2*>(x8A + 4 * g);
        float2 x8b = *reinterpret_cast<const float2*>(x8B + 4 * g);
        ull wd;
        wd = dup2(wv.x);   // df=0, do=0
        A00 = ffma2(rA0.x, wd, A00); A01 = ffma2(rA1.x, wd, A01);
        A02 = ffma2(rA2.x, wd, A02); A03 = ffma2(rA3.x, wd, A03);
        B00 = ffma2(rB0.x, wd, B00); B01 = ffma2(rB1.x, wd, B01);
        B02 = ffma2(rB2.x, wd, B02); B03 = ffma2(rB3.x, wd, B03);
        wd = dup2(wv.y);   // df=0, do=1
        A10 = ffma2(rA0.x, wd, A10); A11 = ffma2(rA1.x, wd, A11);
        A12 = ffma2(rA2.x, wd, A12); A13 = ffma2(rA3.x, wd, A13);
        B10 = ffma2(rB0.x, wd, B10); B11 = ffma2(rB1.x, wd, B11);
        B12 = ffma2(rB2.x, wd, B12); B13 = ffma2(rB3.x, wd, B13);
        wd = dup2(wv.z);   // df=1, do=0
        A00 = ffma2(rA0.y, wd, A00); A01 = ffma2(rA1.y, wd, A01);
        A02 = ffma2(rA2.y, wd, A02); A03 = ffma2(rA3.y, wd, A03);
        B00 = ffma2(rB0.y, wd, B00); B01 = ffma2(rB1.y, wd, B01);
        B02 = ffma2(rB2.y, wd, B02); B03 = ffma2(rB3.y, wd, B03);
        wd = dup2(wv.w);   // df=1, do=1
        A10 = ffma2(rA0.y, wd, A10); A11 = ffma2(rA1.y, wd, A11);
        A12 = ffma2(rA2.y, wd, A12); A13 = ffma2(rA3.y, wd, A13);
        B10 = ffma2(rB0.y, wd, B10); B11 = ffma2(rB1.y, wd, B11);
        B12 = ffma2(rB2.y, wd, B12); B13 = ffma2(rB3.y, wd, B13);
        // s=8 scalar path
        A80 = fmaf(wv.x, x8a.x, A80); A80 = fmaf(wv.z, x8a.y, A80);
        A81 = fmaf(wv.y, x8a.x, A81); A81 = fmaf(wv.w, x8a.y, A81);
        B80 = fmaf(wv.x, x8b.x, B80); B80 = fmaf(wv.z, x8b.y, B80);
        B81 = fmaf(wv.y, x8b.x, B81); B81 = fmaf(wv.w, x8b.y, B81);
    }

    // combine fh halves (one xor-16 round)
    A00 = fadd2(A00, __shfl_xor_sync(0xffffffffu, A00, 16));
    A01 = fadd2(A01, __shfl_xor_sync(0xffffffffu, A01, 16));
    A02 = fadd2(A02, __shfl_xor_sync(0xffffffffu, A02, 16));
    A03 = fadd2(A03, __shfl_xor_sync(0xffffffffu, A03, 16));
    A10 = fadd2(A10, __shfl_xor_sync(0xffffffffu, A10, 16));
    A11 = fadd2(A11, __shfl_xor_sync(0xffffffffu, A11, 16));
    A12 = fadd2(A12, __shfl_xor_sync(0xffffffffu, A12, 16));
    A13 = fadd2(A13, __shfl_xor_sync(0xffffffffu, A13, 16));
    A80 += __shfl_xor_sync(0xffffffffu, A80, 16);
    A81 += __shfl_xor_sync(0xffffffffu, A81, 16);
    B00 = fadd2(B00, __shfl_xor_sync(0xffffffffu, B00, 16));
    B01 = fadd2(B01, __shfl_xor_sync(0xffffffffu, B01, 16));
    B02 = fadd2(B02, __shfl_xor_sync(0xffffffffu, B02, 16));
    B03 = fadd2(B03, __shfl_xor_sync(0xffffffffu, B03, 16));
    B10 = fadd2(B10, __shfl_xor_sync(0xffffffffu, B10, 16));
    B11 = fadd2(B11, __shfl_xor_sync(0xffffffffu, B11, 16));
    B12 = fadd2(B12, __shfl_xor_sync(0xffffffffu, B12, 16));
    B13 = fadd2(B13, __shfl_xor_sync(0xffffffffu, B13, 16));
    B80 += __shfl_xor_sync(0xffffffffu, B80, 16);
    B81 += __shfl_xor_sync(0xffffffffu, B81, 16);

    // epilogue per batch (psA/scp reused with syncs)
    #pragma unroll
    for (int bi = 0; bi < 2; ++bi) {
        if (fh == 0) {
            int o0 = 2 * op, o1 = 2 * op + 1;
            if (bi == 0) {
                *reinterpret_cast<ull*>(&psA[((w * 4 + 0) * 32 + o0) * 2]) = A00;
                *reinterpret_cast<ull*>(&psA[((w * 4 + 1) * 32 + o0) * 2]) = A01;
                *reinterpret_cast<ull*>(&psA[((w * 4 + 2) * 32 + o0) * 2]) = A02;
                *reinterpret_cast<ull*>(&psA[((w * 4 + 3) * 32 + o0) * 2]) = A03;
                ps8[w * 32 + o0] = A80;
                *reinterpret_cast<ull*>(&psA[((w * 4 + 0) * 32 + o1) * 2]) = A10;
                *reinterpret_cast<ull*>(&psA[((w * 4 + 1) * 32 + o1) * 2]) = A11;
                *reinterpret_cast<ull*>(&psA[((w * 4 + 2) * 32 + o1) * 2]) = A12;
                *reinterpret_cast<ull*>(&psA[((w * 4 + 3) * 32 + o1) * 2]) = A13;
                ps8[w * 32 + o1] = A81;
            } else {
                *reinterpret_cast<ull*>(&psA[((w * 4 + 0) * 32 + o0) * 2]) = B00;
                *reinterpret_cast<ull*>(&psA[((w * 4 + 1) * 32 + o0) * 2]) = B01;
                *reinterpret_cast<ull*>(&psA[((w * 4 + 2) * 32 + o0) * 2]) = B02;
                *reinterpret_cast<ull*>(&psA[((w * 4 + 3) * 32 + o0) * 2]) = B03;
                ps8[w * 32 + o0] = B80;
                *reinterpret_cast<ull*>(&psA[((w * 4 + 0) * 32 + o1) * 2]) = B10;
                *reinterpret_cast<ull*>(&psA[((w * 4 + 1) * 32 + o1) * 2]) = B11;
                *reinterpret_cast<ull*>(&psA[((w * 4 + 2) * 32 + o1) * 2]) = B12;
                *reinterpret_cast<ull*>(&psA[((w * 4 + 3) * 32 + o1) * 2]) = B13;
                ps8[w * 32 + o1] = B81;
            }
        }
        __syncthreads();

        // finalize: sum 8 warp-partials -> h -> pnorm -> score partials
        for (int v = tid; v < SS * H1; v += 256) {
            int s = v >> 5, o = v & 31;
            float hh = 0.f;
            if (s == 8) {
                #pragma unroll
                for (int ww = 0; ww < 8; ++ww) hh += ps8[ww * 32 + o];
            } else {
                int sp = s >> 1, part = s & 1;
                #pragma unroll
                for (int ww = 0; ww < 8; ++ww)
                    hh += psA[((ww * 4 + sp) * 32 + o) * 2 + part];
            }
            hh += b1[t * H1 + o];
            float pn = pnorm1(hh, gamma1[t * H1 + o], beta1[t * H1 + o]);
            scp[s * 33 + o] = pn * g_W2r[t * H1 + o];
        }
        __syncthreads();

        // softmax over s (warp 0)
        if (tid < 32) {
            float sc = -3.0e38f;
            if (lane < SS) {
                float s0 = 0.f;
                #pragma unroll
                for (int o = 0; o < H1; ++o) s0 += scp[lane * 33 + o];
                sc = s0;
            }
            float mx = sc;
            #pragma unroll
            for (int d = 16; d; d >>= 1) mx = fmaxf(mx, __shfl_xor_sync(0xffffffffu, mx, d));
            float e = (lane < SS) ? expf(sc - mx) : 0.f;
            float se = e;
            #pragma unroll
            for (int d = 16; d; d >>= 1) se += __shfl_xor_sync(0xffffffffu, se, d);
            float q = e / se;
            float qt = q;
            #pragma unroll
            for (int d = 16; d; d >>= 1) qt += __shfl_xor_sync(0xffffffffu, qt, d);
            if (lane < SS) qsm[lane] = q;
            if (lane == 0) g_tq[(b0 + bi) * TT + t] = qt * (1.0f / SS);
        }
        __syncthreads();

        // team_out[f] = sum_s q[s] * x[s][f]  (f-pair per thread)
        {
            float* tout = g_team + ((size_t)(b0 + bi) * TT + t) * FF;
            const float* xs = xsp[bi];
            const float* x8 = xs8[bi];
            float q0 = qsm[0], q1 = qsm[1], q2 = qsm[2], q3 = qsm[3], q4 = qsm[4],
                  q5 = qsm[5], q6 = qsm[6], q7 = qsm[7], q8 = qsm[8];
            int f2 = 2 * tid;
            ulonglong2 u0 = *reinterpret_cast<const ulonglong2*>(&xs[0 * XROW + 2 * f2]);
            ulonglong2 u1 = *reinterpret_cast<const ulonglong2*>(&xs[1 * XROW + 2 * f2]);
            ulonglong2 u2 = *reinterpret_cast<const ulonglong2*>(&xs[2 * XROW + 2 * f2]);
            ulonglong2 u3 = *reinterpret_cast<const ulonglong2*>(&xs[3 * XROW + 2 * f2]);
            float2 x8v = *reinterpret_cast<const float2*>(&x8[f2]);
            float o0 = q8 * x8v.x, o1 = q8 * x8v.y;
            float2 a;
            a = u2f(u0.x); o0 = fmaf(q0, a.x, o0); o0 = fmaf(q1, a.y, o0);
            a = u2f(u0.y); o1 = fmaf(q0, a.x, o1); o1 = fmaf(q1, a.y, o1);
            a = u2f(u1.x); o0 = fmaf(q2, a.x, o0); o0 = fmaf(q3, a.y, o0);
            a = u2f(u1.y); o1 = fmaf(q2, a.x, o1); o1 = fmaf(q3, a.y, o1);
            a = u2f(u2.x); o0 = fmaf(q4, a.x, o0); o0 = fmaf(q5, a.y, o0);
            a = u2f(u2.y); o1 = fmaf(q4, a.x, o1); o1 = fmaf(q5, a.y, o1);
            a = u2f(u3.x); o0 = fmaf(q6, a.x, o0); o0 = fmaf(q7, a.y, o0);
            a = u2f(u3.y); o1 = fmaf(q6, a.x, o1); o1 = fmaf(q7, a.y, o1);
            *reinterpret_cast<float2*>(&tout[f2]) = make_float2(o0, o1);
        }
        __syncthreads();   // protect psA/scp before next bi
    }
}

// per weight scalar (k2 mainloop): 4 packed FFMA2 over t-pairs + 1 scalar FMA for t=8
#define PROCC(wc, oc) { \
    ull wd = dup2(wc); \
    acc[oc][0] = ffma2(a0, wd, acc[oc][0]); \
    acc[oc][1] = ffma2(a1, wd, acc[oc][1]); \
    acc[oc][2] = ffma2(a2, wd, acc[oc][2]); \
    acc[oc][3] = ffma2(a3, wd, acc[oc][3]); \
    acc8[oc] = fmaf(wc, x8, acc8[oc]); }

// ---------------- kernel 2: per b (unchanged from 537-proven version) ----------------
__global__ __launch_bounds__(256, 3) void k2(const float* __restrict__ mb1,
                                             const float* __restrict__ mgamma,
                                             const float* __restrict__ mbeta,
                                             const float* __restrict__ cc,
                                             const float* __restrict__ rc,
                                             const float* __restrict__ ic,
                                             float* __restrict__ out)
{
    __shared__ float tsp[4 * XROW];
    __shared__ float ts8[FF + 8];
    __shared__ float hs2[H2 * 12];       // [o][t] pad12
    __shared__ float msp[9 * 65];
    __shared__ float mwm[16];

    const int b = blockIdx.x;
    const int tid = threadIdx.x, lane = tid & 31, w = tid >> 5;

    // stage team_out (coalesced read, pair-layout write)
    const float4* tin4 = reinterpret_cast<const float4*>(g_team + (size_t)b * TT * FF);
    #pragma unroll 2
    for (int i = tid; i < TT * FF / 4; i += 256) {
        int tt = i >> 7, fq = i & 127, f = 4 * fq;
        float4 v = tin4[i];
        if (tt == 8) {
            *reinterpret_cast<float4*>(&ts8[f]) = v;
        } else {
            int sp = tt >> 1, hf = tt & 1;
            tsp[sp * XROW + 2 * (f + 0) + hf] = v.x;
            tsp[sp * XROW + 2 * (f + 1) + hf] = v.y;
            tsp[sp * XROW + 2 * (f + 2) + hf] = v.z;
            tsp[sp * XROW + 2 * (f + 3) + hf] = v.w;
        }
    }
    __syncthreads();

    // two passes: warp w covers o-quads w and 8+w
    #pragma unroll
    for (int pass = 0; pass < 2; ++pass) {
        int q = 8 * pass + w;
        ull acc[4][4];
        float acc8[4];
        #pragma unroll
        for (int oc = 0; oc < 4; ++oc) {
            acc8[oc] = 0.f;
            #pragma unroll
            for (int sp = 0; sp < 4; ++sp) acc[oc][sp] = 0ull;
        }
        const float4* wb = reinterpret_cast<const float4*>(g_mW1b)
                         + ((size_t)q * 16) * 32 + lane;
        #pragma unroll
        for (int step = 0; step < 16; ++step) {
            float4 wv = wb[step * 32];
            int f = step * 32 + lane;
            ull a0 = *reinterpret_cast<const ull*>(&tsp[0 * XROW + 2 * f]);
            ull a1 = *reinterpret_cast<const ull*>(&tsp[1 * XROW + 2 * f]);
            ull a2 = *reinterpret_cast<const ull*>(&tsp[2 * XROW + 2 * f]);
            ull a3 = *reinterpret_cast<const ull*>(&tsp[3 * XROW + 2 * f]);
            float x8 = ts8[f];
            PROCC(wv.x, 0) PROCC(wv.y, 1) PROCC(wv.z, 2) PROCC(wv.w, 3)
        }
        #pragma unroll
        for (int r = 16; r >= 1; r >>= 1) {
            #pragma unroll
            for (int oc = 0; oc < 4; ++oc) {
                #pragma unroll
                for (int sp = 0; sp < 4; ++sp)
                    acc[oc][sp] = fadd2(acc[oc][sp],
                                        __shfl_xor_sync(0xffffffffu, acc[oc][sp], r));
                acc8[oc] += __shfl_xor_sync(0xffffffffu, acc8[oc], r);
            }
        }
        if (lane == 0) {
            #pragma unroll
            for (int oc = 0; oc < 4; ++oc) {
                int o = 4 * q + oc;
                #pragma unroll
                for (int sp = 0; sp < 4; ++sp)
                    *reinterpret_cast<ull*>(&hs2[o * 12 + 2 * sp]) = acc[oc][sp];
                hs2[o * 12 + 8] = acc8[oc];
            }
        }
    }
    __syncthreads();

    // finalize
    for (int v = tid; v < TT * H2; v += 256) {
        int tt = v >> 6, o = v & 63;
        float hh = hs2[o * 12 + tt] + mb1[o];
        float pn = pnorm1(hh, mgamma[o], mbeta[o]);
        msp[tt * 65 + o] = pn * g_mW2r[o];
    }
    __syncthreads();

    // softmax over t + penalty (warp 0)
    if (tid < 32) {
        float sc = -3.0e38f;
        if (lane < TT) {
            float s0 = 0.f;
            #pragma unroll
            for (int o = 0; o < H2; ++o) s0 += msp[lane * 65 + o];
            sc = s0;
        }
        float mx = sc;
        #pragma unroll
        for (int d = 16; d; d >>= 1) mx = fmaxf(mx, __shfl_xor_sync(0xffffffffu, mx, d));
        float e = (lane < TT) ? expf(sc - mx) : 0.f;
        float se = e;
        #pragma unroll
        for (int d = 16; d; d >>= 1) se += __shfl_xor_sync(0xffffffffu, se, d);
        float mwq = e / se;

        float tq = (lane < TT) ? g_tq[b * TT + lane] : 0.f;
        float ts = tq;
        #pragma unroll
        for (int d = 16; d; d >>= 1) ts += __shfl_xor_sync(0xffffffffu, ts, d);
        float mean = ts * (1.0f / TT);
        float dv = (lane < TT) ? (tq - mean) * (tq - mean) : 0.f;
        float vs = dv;
        #pragma unroll
        for (int d = 16; d; d >>= 1) vs += __shfl_xor_sync(0xffffffffu, vs, d);
        float var = vs * (1.0f / (TT - 1));
        float nv = var / (mean * mean + 1e-8f);
        float total = cc[0] * (float)(TT * (TT - 1) / 2) + rc[0] * (float)TT
                    + ic[0] * (float)TT * (1.0f + nv);
        float pen = fminf(total, 0.5f);
        if (lane < TT) mwm[lane] = mwq * (1.0f - pen);
    }
    __syncthreads();

    float* ob = out + (size_t)b * FF;
    float m0 = mwm[0], m1 = mwm[1], m2 = mwm[2], m3 = mwm[3], m4 = mwm[4],
          m5 = mwm[5], m6 = mwm[6], m7 = mwm[7], m8 = mwm[8];
    for (int f = tid; f < FF; f += 256) {
        float2 v0 = *reinterpret_cast<const float2*>(&tsp[0 * XROW + 2 * f]);
        float2 v1 = *reinterpret_cast<const float2*>(&tsp[1 * XROW + 2 * f]);
        float2 v2 = *reinterpret_cast<const float2*>(&tsp[2 * XROW + 2 * f]);
        float2 v3 = *reinterpret_cast<const float2*>(&tsp[3 * XROW + 2 * f]);
        float o = m8 * ts8[f];
        o = fmaf(m0, v0.x, o); o = fmaf(m1, v0.y, o);
        o = fmaf(m2, v1.x, o); o = fmaf(m3, v1.y, o);
        o = fmaf(m4, v2.x, o); o = fmaf(m5, v2.y, o);
        o = fmaf(m6, v3.x, o); o = fmaf(m7, v3.y, o);
        ob[f] = o;
    }
}

// ---------------- launch ----------------
extern "C" void kernel_launch(void* const* d_in, const int* in_sizes, int n_in,
                              void* d_out, int out_size)
{
    const float* path   = (const float*)d_in[0];
    const float* W1     = (const float*)d_in[1];
    const float* b1     = (const float*)d_in[2];
    const float* ang1   = (const float*)d_in[3];
    const float* gamma1 = (const float*)d_in[4];
    const float* beta1  = (const float*)d_in[5];
    const float* W2     = (const float*)d_in[6];
    // d_in[7] = b2 (softmax-invariant, unused)
    const float* ang2   = (const float*)d_in[8];
    const float* mW1    = (const float*)d_in[9];
    const float* mb1    = (const float*)d_in[10];
    const float* mang1  = (const float*)d_in[11];
    const float* mgamma = (const float*)d_in[12];
    const float* mbeta  = (const float*)d_in[13];
    const float* mW2    = (const float*)d_in[14];
    // d_in[15] = mb2 (softmax-invariant, unused)
    const float* mang2  = (const float*)d_in[16];
    const float* cc     = (const float*)d_in[17];
    const float* rc     = (const float*)d_in[18];
    const float* ic     = (const float*)d_in[19];
    (void)n_in; (void)out_size;

    int B = in_sizes[0] / (FF * TT * SS);

    // dummy launches so ncu's bounded capture lands on k1
    kalign<<<1, 32>>>();
    kalign<<<1, 32>>>();

    int prepN = TT * 16384 + TT * H1 + 32768 + H2;
    kprep<<<(prepN + 255) / 256, 256>>>(W1, ang1, W2, ang2, mW1, mang1, mW2, mang2);

    dim3 g1(TT, B / 2);
    k1<<<g1, 256>>>(path, b1, gamma1, beta1);
    k2<<<B, 256>>>(mb1, mgamma, mbeta, cc, rc, ic, (float*)d_out);
}

// round 14
// speedup vs baseline: 1.5160x; 1.5160x over previous
#include <cuda_runtime.h>
#include <cstddef>

#define TT 9
#define SS 9
#define FF 512
#define H1 32
#define H2 64
#define XROW 1032          // floats per s-pair row (2*FF + 8 pad)
#define BASE7 7.0f

typedef unsigned long long ull;

// ---------------- device scratch ----------------
__device__ float g_W1p [TT * 8 * 16 * 32 * 4];   // rotated W1: [t][w8][g16][lane32][c4]
                                                 // lane=(fh<<4|op), c=(df<<1|do)
                                                 // f = w*64+g*4+fh*2+df, o = op*2+do
__device__ float g_W2r [TT * H1];
__device__ float g_mW1p[2 * 8 * 16 * 32 * 4];    // rotated mW1: [hh2][w8][g16][lane32][c4]
                                                 // f = w*64+g*4+fh*2+df, o = 32*hh+op*2+do
__device__ float g_mW2r[H2];
__device__ float g_team[4096 * TT * FF];
__device__ float g_tq  [4096 * TT];
__device__ float g_sink;

// ---------------- profiling-alignment dummies (ncu capture lands on k1) ----------------
__global__ void kalign() {
    if (threadIdx.x == 0xFFFFFFFFu) g_sink = 0.0f;
}

// ---------------- f32x2 helpers ----------------
__device__ __forceinline__ ull ffma2(ull a, ull b, ull c) {
    ull d;
    asm("fma.rn.f32x2 %0, %1, %2, %3;" : "=l"(d) : "l"(a), "l"(b), "l"(c));
    return d;
}
__device__ __forceinline__ ull fadd2(ull a, ull b) {
    ull d;
    asm("add.rn.f32x2 %0, %1, %2;" : "=l"(d) : "l"(a), "l"(b));
    return d;
}
__device__ __forceinline__ ull dup2(float x) {
    ull r;
    asm("mov.b64 %0, {%1, %1};" : "=l"(r) : "f"(x));
    return r;
}
__device__ __forceinline__ float2 u2f(ull r) {
    float2 v;
    asm("mov.b64 {%0, %1}, %2;" : "=f"(v.x), "=f"(v.y) : "l"(r));
    return v;
}

__device__ __forceinline__ float pnorm1(float h, float g, float b) {
    float m = h - BASE7 * floorf(h * (1.0f / BASE7));
    return g * ((m - 3.5f) * (1.0f / 3.5f)) + b;
}

// rotate-absorb: coeff of x_f in dot(rot(x), Wrow)
__device__ __forceinline__ float rotv(const float* __restrict__ Wrow,
                                      const float* __restrict__ ang,
                                      int f, int nplanes) {
    if (f >= 2 * nplanes) return Wrow[f];
    int p = f >> 1; float a = ang[p];
    float c = cosf(a), s = sinf(a);
    float w0 = Wrow[2 * p], w1 = Wrow[2 * p + 1];
    return (f & 1) ? (c * w1 - s * w0) : (c * w0 + s * w1);
}

// ---------------- prep: rotate + re-tile weights ----------------
__global__ void kprep(const float* __restrict__ W1, const float* __restrict__ ang1,
                      const float* __restrict__ W2, const float* __restrict__ ang2,
                      const float* __restrict__ mW1, const float* __restrict__ mang1,
                      const float* __restrict__ mW2, const float* __restrict__ mang2)
{
    int idx = blockIdx.x * 256 + threadIdx.x;
    const int N1 = TT * 16384;     // g_W1p
    const int N2 = TT * H1;        // g_W2r
    const int N3 = 32768;          // g_mW1p
    const int N4 = H2;             // g_mW2r
    if (idx < N1) {
        int c    =  idx        & 3;
        int lane = (idx >> 2)  & 31;
        int g    = (idx >> 7)  & 15;
        int w    = (idx >> 11) & 7;
        int t    =  idx >> 14;
        int op = lane & 15, fh = lane >> 4;
        int df = c >> 1, dd = c & 1;
        int f = w * 64 + g * 4 + fh * 2 + df;
        int o = op * 2 + dd;
        g_W1p[idx] = rotv(W1 + ((size_t)t * H1 + o) * FF, ang1 + 2 * t, f, 2);
    } else if (idx < N1 + N2) {
        int jj = idx - N1; int t = jj / H1, o = jj - t * H1;
        g_W2r[jj] = rotv(W2 + t * H1, ang2 + 2 * t, o, 2);
    } else if (idx < N1 + N2 + N3) {
        int jj = idx - N1 - N2;
        int c    =  jj        & 3;
        int lane = (jj >> 2)  & 31;
        int g    = (jj >> 7)  & 15;
        int w    = (jj >> 11) & 7;
        int hh   = (jj >> 14) & 1;
        int op = lane & 15, fh = lane >> 4;
        int df = c >> 1, dd = c & 1;
        int f = w * 64 + g * 4 + fh * 2 + df;
        int o = 32 * hh + op * 2 + dd;
        g_mW1p[jj] = rotv(mW1 + (size_t)o * FF, mang1, f, 4);
    } else if (idx < N1 + N2 + N3 + N4) {
        int o = idx - N1 - N2 - N3;
        g_mW2r[o] = rotv(mW2, mang2, o, 2);
    }
}

// ---------------- kernel 1: per (b,t) — o-pair lanes (R12-proven, 416us) ----------------
__global__ __launch_bounds__(256, 5) void k1(const float* __restrict__ path,
                                             const float* __restrict__ b1,
                                             const float* __restrict__ gamma1,
                                             const float* __restrict__ beta1)
{
    __shared__ float xsp[4 * XROW];          // s-pair rows: (x[2sp][f], x[2sp+1][f])
    __shared__ float xs8[FF + 8];            // s=8 row
    __shared__ float psA[8 * 4 * 32 * 2];    // warp partials: [w][sp][o]{lo,hi}
    __shared__ float ps8[8 * 32];            // warp partials s=8: [w][o]
    __shared__ float scp[SS * 33];           // score partials
    __shared__ float qsm[16];

    const int t = blockIdx.x, b = blockIdx.y;
    const int tid = threadIdx.x, lane = tid & 31, w = tid >> 5;
    const int op = lane & 15, fh = lane >> 4;

    // stage x: pair layout (incremental f,s — no per-iter division)
    {
        const float* xb = path + (size_t)b * (FF * TT * SS) + t * SS;
        int f = tid / 9;
        int s = tid - f * 9;
        const float* p = xb + f * (TT * SS) + s;
        #pragma unroll
        for (int it = 0; it < 18; ++it) {
            float v = *p;
            if (s == 8) xs8[f] = v;
            else xsp[(s >> 1) * XROW + 2 * f + (s & 1)] = v;
            s += 4; f += 28;
            if (s >= 9) { s -= 9; f += 1; p += 29 * (TT * SS) - 5; }
            else        {                p += 28 * (TT * SS) + 4; }
        }
    }
    __syncthreads();

    // mainloop: lane owns o-pair {2op, 2op+1}; warp w covers f in [64w, 64w+64);
    // lane's f-pairs: f = 64w + 4g + 2fh + {0,1}
    ull acc00 = 0, acc01 = 0, acc02 = 0, acc03 = 0;   // do=0, sp 0..3
    ull acc10 = 0, acc11 = 0, acc12 = 0, acc13 = 0;   // do=1
    float acc80 = 0.f, acc81 = 0.f;

    const float4* wq = reinterpret_cast<const float4*>(g_W1p)
                     + ((size_t)(t * 8 + w) * 16) * 32 + lane;
    const float* xb0 = xsp + 2 * (w * 64 + 2 * fh);
    const float* x8b = xs8 + (w * 64 + 2 * fh);

    #pragma unroll
    for (int g = 0; g < 16; ++g) {
        float4 wv = wq[g * 32];
        const float* xg = xb0 + 8 * g;
        ulonglong2 r0 = *reinterpret_cast<const ulonglong2*>(xg + 0 * XROW);
        ulonglong2 r1 = *reinterpret_cast<const ulonglong2*>(xg + 1 * XROW);
        ulonglong2 r2 = *reinterpret_cast<const ulonglong2*>(xg + 2 * XROW);
        ulonglong2 r3 = *reinterpret_cast<const ulonglong2*>(xg + 3 * XROW);
        float2 x8v = *reinterpret_cast<const float2*>(x8b + 4 * g);
        ull wd;
        // df = 0 (r.x components)
        wd = dup2(wv.x);
        acc00 = ffma2(r0.x, wd, acc00); acc01 = ffma2(r1.x, wd, acc01);
        acc02 = ffma2(r2.x, wd, acc02); acc03 = ffma2(r3.x, wd, acc03);
        acc80 = fmaf(wv.x, x8v.x, acc80);
        wd = dup2(wv.y);
        acc10 = ffma2(r0.x, wd, acc10); acc11 = ffma2(r1.x, wd, acc11);
        acc12 = ffma2(r2.x, wd, acc12); acc13 = ffma2(r3.x, wd, acc13);
        acc81 = fmaf(wv.y, x8v.x, acc81);
        // df = 1 (r.y components)
        wd = dup2(wv.z);
        acc00 = ffma2(r0.y, wd, acc00); acc01 = ffma2(r1.y, wd, acc01);
        acc02 = ffma2(r2.y, wd, acc02); acc03 = ffma2(r3.y, wd, acc03);
        acc80 = fmaf(wv.z, x8v.y, acc80);
        wd = dup2(wv.w);
        acc10 = ffma2(r0.y, wd, acc10); acc11 = ffma2(r1.y, wd, acc11);
        acc12 = ffma2(r2.y, wd, acc12); acc13 = ffma2(r3.y, wd, acc13);
        acc81 = fmaf(wv.w, x8v.y, acc81);
    }

    // combine fh halves (one xor-16 round), lanes 0..15 hold warp totals
    acc00 = fadd2(acc00, __shfl_xor_sync(0xffffffffu, acc00, 16));
    acc01 = fadd2(acc01, __shfl_xor_sync(0xffffffffu, acc01, 16));
    acc02 = fadd2(acc02, __shfl_xor_sync(0xffffffffu, acc02, 16));
    acc03 = fadd2(acc03, __shfl_xor_sync(0xffffffffu, acc03, 16));
    acc10 = fadd2(acc10, __shfl_xor_sync(0xffffffffu, acc10, 16));
    acc11 = fadd2(acc11, __shfl_xor_sync(0xffffffffu, acc11, 16));
    acc12 = fadd2(acc12, __shfl_xor_sync(0xffffffffu, acc12, 16));
    acc13 = fadd2(acc13, __shfl_xor_sync(0xffffffffu, acc13, 16));
    acc80 += __shfl_xor_sync(0xffffffffu, acc80, 16);
    acc81 += __shfl_xor_sync(0xffffffffu, acc81, 16);

    if (fh == 0) {
        int o0 = 2 * op, o1 = 2 * op + 1;
        *reinterpret_cast<ull*>(&psA[((w * 4 + 0) * 32 + o0) * 2]) = acc00;
        *reinterpret_cast<ull*>(&psA[((w * 4 + 1) * 32 + o0) * 2]) = acc01;
        *reinterpret_cast<ull*>(&psA[((w * 4 + 2) * 32 + o0) * 2]) = acc02;
        *reinterpret_cast<ull*>(&psA[((w * 4 + 3) * 32 + o0) * 2]) = acc03;
        ps8[w * 32 + o0] = acc80;
        *reinterpret_cast<ull*>(&psA[((w * 4 + 0) * 32 + o1) * 2]) = acc10;
        *reinterpret_cast<ull*>(&psA[((w * 4 + 1) * 32 + o1) * 2]) = acc11;
        *reinterpret_cast<ull*>(&psA[((w * 4 + 2) * 32 + o1) * 2]) = acc12;
        *reinterpret_cast<ull*>(&psA[((w * 4 + 3) * 32 + o1) * 2]) = acc13;
        ps8[w * 32 + o1] = acc81;
    }
    __syncthreads();

    // finalize: sum 8 warp-partials -> h -> pnorm -> score partials
    for (int v = tid; v < SS * H1; v += 256) {
        int s = v >> 5, o = v & 31;
        float hh = 0.f;
        if (s == 8) {
            #pragma unroll
            for (int ww = 0; ww < 8; ++ww) hh += ps8[ww * 32 + o];
        } else {
            int sp = s >> 1, part = s & 1;
            #pragma unroll
            for (int ww = 0; ww < 8; ++ww)
                hh += psA[((ww * 4 + sp) * 32 + o) * 2 + part];
        }
        hh += b1[t * H1 + o];
        float pn = pnorm1(hh, gamma1[t * H1 + o], beta1[t * H1 + o]);
        scp[s * 33 + o] = pn * g_W2r[t * H1 + o];
    }
    __syncthreads();

    // softmax over s (warp 0)
    if (tid < 32) {
        float sc = -3.0e38f;
        if (lane < SS) {
            float s0 = 0.f;
            #pragma unroll
            for (int o = 0; o < H1; ++o) s0 += scp[lane * 33 + o];
            sc = s0;
        }
        float mx = sc;
        #pragma unroll
        for (int d = 16; d; d >>= 1) mx = fmaxf(mx, __shfl_xor_sync(0xffffffffu, mx, d));
        float e = (lane < SS) ? expf(sc - mx) : 0.f;
        float se = e;
        #pragma unroll
        for (int d = 16; d; d >>= 1) se += __shfl_xor_sync(0xffffffffu, se, d);
        float q = e / se;
        float qt = q;
        #pragma unroll
        for (int d = 16; d; d >>= 1) qt += __shfl_xor_sync(0xffffffffu, qt, d);
        if (lane < SS) qsm[lane] = q;
        if (lane == 0) g_tq[b * TT + t] = qt * (1.0f / SS);
    }
    __syncthreads();

    // team_out[f] = sum_s q[s] * x[s][f]  (f-pair per thread, one pass)
    {
        float* tout = g_team + ((size_t)b * TT + t) * FF;
        float q0 = qsm[0], q1 = qsm[1], q2 = qsm[2], q3 = qsm[3], q4 = qsm[4],
              q5 = qsm[5], q6 = qsm[6], q7 = qsm[7], q8 = qsm[8];
        int f2 = 2 * tid;   // 0..510
        ulonglong2 u0 = *reinterpret_cast<const ulonglong2*>(&xsp[0 * XROW + 2 * f2]);
        ulonglong2 u1 = *reinterpret_cast<const ulonglong2*>(&xsp[1 * XROW + 2 * f2]);
        ulonglong2 u2 = *reinterpret_cast<const ulonglong2*>(&xsp[2 * XROW + 2 * f2]);
        ulonglong2 u3 = *reinterpret_cast<const ulonglong2*>(&xsp[3 * XROW + 2 * f2]);
        float2 x8v = *reinterpret_cast<const float2*>(&xs8[f2]);
        float o0 = q8 * x8v.x, o1 = q8 * x8v.y;
        float2 a;
        a = u2f(u0.x); o0 = fmaf(q0, a.x, o0); o0 = fmaf(q1, a.y, o0);
        a = u2f(u0.y); o1 = fmaf(q0, a.x, o1); o1 = fmaf(q1, a.y, o1);
        a = u2f(u1.x); o0 = fmaf(q2, a.x, o0); o0 = fmaf(q3, a.y, o0);
        a = u2f(u1.y); o1 = fmaf(q2, a.x, o1); o1 = fmaf(q3, a.y, o1);
        a = u2f(u2.x); o0 = fmaf(q4, a.x, o0); o0 = fmaf(q5, a.y, o0);
        a = u2f(u2.y); o1 = fmaf(q4, a.x, o1); o1 = fmaf(q5, a.y, o1);
        a = u2f(u3.x); o0 = fmaf(q6, a.x, o0); o0 = fmaf(q7, a.y, o0);
        a = u2f(u3.y); o1 = fmaf(q6, a.x, o1); o1 = fmaf(q7, a.y, o1);
        *reinterpret_cast<float2*>(&tout[f2]) = make_float2(o0, o1);
    }
}

// ---------------- kernel 2: per b — o-pair lanes, two H2 halves ----------------
__global__ __launch_bounds__(256, 4) void k2(const float* __restrict__ mb1,
                                             const float* __restrict__ mgamma,
                                             const float* __restrict__ mbeta,
                                             const float* __restrict__ cc,
                                             const float* __restrict__ rc,
                                             const float* __restrict__ ic,
                                             float* __restrict__ out)
{
    __shared__ float tsp[4 * XROW];          // team t-pair rows
    __shared__ float ts8[FF + 8];            // t=8 row
    __shared__ float psA[8 * 4 * 32 * 2];    // warp partials (reused per half)
    __shared__ float ps8[8 * 32];
    __shared__ float msp[9 * 65];            // score partials (full H2)
    __shared__ float mwm[16];

    const int b = blockIdx.x;
    const int tid = threadIdx.x, lane = tid & 31, w = tid >> 5;
    const int op = lane & 15, fh = lane >> 4;

    // stage team_out (coalesced read, pair-layout write)
    const float4* tin4 = reinterpret_cast<const float4*>(g_team + (size_t)b * TT * FF);
    #pragma unroll 2
    for (int i = tid; i < TT * FF / 4; i += 256) {
        int tt = i >> 7, fq = i & 127, f = 4 * fq;
        float4 v = tin4[i];
        if (tt == 8) {
            *reinterpret_cast<float4*>(&ts8[f]) = v;
        } else {
            int sp = tt >> 1, hf = tt & 1;
            tsp[sp * XROW + 2 * (f + 0) + hf] = v.x;
            tsp[sp * XROW + 2 * (f + 1) + hf] = v.y;
            tsp[sp * XROW + 2 * (f + 2) + hf] = v.z;
            tsp[sp * XROW + 2 * (f + 3) + hf] = v.w;
        }
    }
    __syncthreads();

    // two halves of H2: outputs [32*half, 32*half+32)
    #pragma unroll
    for (int half = 0; half < 2; ++half) {
        ull acc00 = 0, acc01 = 0, acc02 = 0, acc03 = 0;
        ull acc10 = 0, acc11 = 0, acc12 = 0, acc13 = 0;
        float acc80 = 0.f, acc81 = 0.f;

        const float4* wq = reinterpret_cast<const float4*>(g_mW1p)
                         + ((size_t)(half * 8 + w) * 16) * 32 + lane;
        const float* xb0 = tsp + 2 * (w * 64 + 2 * fh);
        const float* x8b = ts8 + (w * 64 + 2 * fh);

        #pragma unroll
        for (int g = 0; g < 16; ++g) {
            float4 wv = wq[g * 32];
            const float* xg = xb0 + 8 * g;
            ulonglong2 r0 = *reinterpret_cast<const ulonglong2*>(xg + 0 * XROW);
            ulonglong2 r1 = *reinterpret_cast<const ulonglong2*>(xg + 1 * XROW);
            ulonglong2 r2 = *reinterpret_cast<const ulonglong2*>(xg + 2 * XROW);
            ulonglong2 r3 = *reinterpret_cast<const ulonglong2*>(xg + 3 * XROW);
            float2 x8v = *reinterpret_cast<const float2*>(x8b + 4 * g);
            ull wd;
            wd = dup2(wv.x);
            acc00 = ffma2(r0.x, wd, acc00); acc01 = ffma2(r1.x, wd, acc01);
            acc02 = ffma2(r2.x, wd, acc02); acc03 = ffma2(r3.x, wd, acc03);
            acc80 = fmaf(wv.x, x8v.x, acc80);
            wd = dup2(wv.y);
            acc10 = ffma2(r0.x, wd, acc10); acc11 = ffma2(r1.x, wd, acc11);
            acc12 = ffma2(r2.x, wd, acc12); acc13 = ffma2(r3.x, wd, acc13);
            acc81 = fmaf(wv.y, x8v.x, acc81);
            wd = dup2(wv.z);
            acc00 = ffma2(r0.y, wd, acc00); acc01 = ffma2(r1.y, wd, acc01);
            acc02 = ffma2(r2.y, wd, acc02); acc03 = ffma2(r3.y, wd, acc03);
            acc80 = fmaf(wv.z, x8v.y, acc80);
            wd = dup2(wv.w);
            acc10 = ffma2(r0.y, wd, acc10); acc11 = ffma2(r1.y, wd, acc11);
            acc12 = ffma2(r2.y, wd, acc12); acc13 = ffma2(r3.y, wd, acc13);
            acc81 = fmaf(wv.w, x8v.y, acc81);
        }

        acc00 = fadd2(acc00, __shfl_xor_sync(0xffffffffu, acc00, 16));
        acc01 = fadd2(acc01, __shfl_xor_sync(0xffffffffu, acc01, 16));
        acc02 = fadd2(acc02, __shfl_xor_sync(0xffffffffu, acc02, 16));
        acc03 = fadd2(acc03, __shfl_xor_sync(0xffffffffu, acc03, 16));
        acc10 = fadd2(acc10, __shfl_xor_sync(0xffffffffu, acc10, 16));
        acc11 = fadd2(acc11, __shfl_xor_sync(0xffffffffu, acc11, 16));
        acc12 = fadd2(acc12, __shfl_xor_sync(0xffffffffu, acc12, 16));
        acc13 = fadd2(acc13, __shfl_xor_sync(0xffffffffu, acc13, 16));
        acc80 += __shfl_xor_sync(0xffffffffu, acc80, 16);
        acc81 += __shfl_xor_sync(0xffffffffu, acc81, 16);

        if (fh == 0) {
            int o0 = 2 * op, o1 = 2 * op + 1;
            *reinterpret_cast<ull*>(&psA[((w * 4 + 0) * 32 + o0) * 2]) = acc00;
            *reinterpret_cast<ull*>(&psA[((w * 4 + 1) * 32 + o0) * 2]) = acc01;
            *reinterpret_cast<ull*>(&psA[((w * 4 + 2) * 32 + o0) * 2]) = acc02;
            *reinterpret_cast<ull*>(&psA[((w * 4 + 3) * 32 + o0) * 2]) = acc03;
            ps8[w * 32 + o0] = acc80;
            *reinterpret_cast<ull*>(&psA[((w * 4 + 0) * 32 + o1) * 2]) = acc10;
            *reinterpret_cast<ull*>(&psA[((w * 4 + 1) * 32 + o1) * 2]) = acc11;
            *reinterpret_cast<ull*>(&psA[((w * 4 + 2) * 32 + o1) * 2]) = acc12;
            *reinterpret_cast<ull*>(&psA[((w * 4 + 3) * 32 + o1) * 2]) = acc13;
            ps8[w * 32 + o1] = acc81;
        }
        __syncthreads();

        // finalize this half: sum 8 warp-partials -> pnorm -> msp
        for (int v = tid; v < TT * 32; v += 256) {
            int tt = v >> 5, oo = v & 31;
            float hv = 0.f;
            if (tt == 8) {
                #pragma unroll
                for (int ww = 0; ww < 8; ++ww) hv += ps8[ww * 32 + oo];
            } else {
                int sp = tt >> 1, part = tt & 1;
                #pragma unroll
                for (int ww = 0; ww < 8; ++ww)
                    hv += psA[((ww * 4 + sp) * 32 + oo) * 2 + part];
            }
            int og = 32 * half + oo;
            hv += mb1[og];
            float pn = pnorm1(hv, mgamma[og], mbeta[og]);
            msp[tt * 65 + og] = pn * g_mW2r[og];
        }
        __syncthreads();   // psA safe to reuse for next half
    }

    // softmax over t + penalty (warp 0)
    if (tid < 32) {
        float sc = -3.0e38f;
        if (lane < TT) {
            float s0 = 0.f;
            #pragma unroll
            for (int o = 0; o < H2; ++o) s0 += msp[lane * 65 + o];
            sc = s0;
        }
        float mx = sc;
        #pragma unroll
        for (int d = 16; d; d >>= 1) mx = fmaxf(mx, __shfl_xor_sync(0xffffffffu, mx, d));
        float e = (lane < TT) ? expf(sc - mx) : 0.f;
        float se = e;
        #pragma unroll
        for (int d = 16; d; d >>= 1) se += __shfl_xor_sync(0xffffffffu, se, d);
        float mwq = e / se;

        float tq = (lane < TT) ? g_tq[b * TT + lane] : 0.f;
        float ts = tq;
        #pragma unroll
        for (int d = 16; d; d >>= 1) ts += __shfl_xor_sync(0xffffffffu, ts, d);
        float mean = ts * (1.0f / TT);
        float dv = (lane < TT) ? (tq - mean) * (tq - mean) : 0.f;
        float vs = dv;
        #pragma unroll
        for (int d = 16; d; d >>= 1) vs += __shfl_xor_sync(0xffffffffu, vs, d);
        float var = vs * (1.0f / (TT - 1));
        float nv = var / (mean * mean + 1e-8f);
        float total = cc[0] * (float)(TT * (TT - 1) / 2) + rc[0] * (float)TT
                    + ic[0] * (float)TT * (1.0f + nv);
        float pen = fminf(total, 0.5f);
        if (lane < TT) mwm[lane] = mwq * (1.0f - pen);
    }
    __syncthreads();

    // final output (f-pair per thread)
    {
        float* ob = out + (size_t)b * FF;
        float m0 = mwm[0], m1 = mwm[1], m2 = mwm[2], m3 = mwm[3], m4 = mwm[4],
              m5 = mwm[5], m6 = mwm[6], m7 = mwm[7], m8 = mwm[8];
        int f2 = 2 * tid;
        ulonglong2 u0 = *reinterpret_cast<const ulonglong2*>(&tsp[0 * XROW + 2 * f2]);
        ulonglong2 u1 = *reinterpret_cast<const ulonglong2*>(&tsp[1 * XROW + 2 * f2]);
        ulonglong2 u2 = *reinterpret_cast<const ulonglong2*>(&tsp[2 * XROW + 2 * f2]);
        ulonglong2 u3 = *reinterpret_cast<const ulonglong2*>(&tsp[3 * XROW + 2 * f2]);
        float2 x8v = *reinterpret_cast<const float2*>(&ts8[f2]);
        float o0 = m8 * x8v.x, o1 = m8 * x8v.y;
        float2 a;
        a = u2f(u0.x); o0 = fmaf(m0, a.x, o0); o0 = fmaf(m1, a.y, o0);
        a = u2f(u0.y); o1 = fmaf(m0, a.x, o1); o1 = fmaf(m1, a.y, o1);
        a = u2f(u1.x); o0 = fmaf(m2, a.x, o0); o0 = fmaf(m3, a.y, o0);
        a = u2f(u1.y); o1 = fmaf(m2, a.x, o1); o1 = fmaf(m3, a.y, o1);
        a = u2f(u2.x); o0 = fmaf(m4, a.x, o0); o0 = fmaf(m5, a.y, o0);
        a = u2f(u2.y); o1 = fmaf(m4, a.x, o1); o1 = fmaf(m5, a.y, o1);
        a = u2f(u3.x); o0 = fmaf(m6, a.x, o0); o0 = fmaf(m7, a.y, o0);
        a = u2f(u3.y); o1 = fmaf(m6, a.x, o1); o1 = fmaf(m7, a.y, o1);
        *reinterpret_cast<float2*>(&ob[f2]) = make_float2(o0, o1);
    }
}

// ---------------- launch ----------------
extern "C" void kernel_launch(void* const* d_in, const int* in_sizes, int n_in,
                              void* d_out, int out_size)
{
    const float* path   = (const float*)d_in[0];
    const float* W1     = (const float*)d_in[1];
    const float* b1     = (const float*)d_in[2];
    const float* ang1   = (const float*)d_in[3];
    const float* gamma1 = (const float*)d_in[4];
    const float* beta1  = (const float*)d_in[5];
    const float* W2     = (const float*)d_in[6];
    // d_in[7] = b2 (softmax-invariant, unused)
    const float* ang2   = (const float*)d_in[8];
    const float* mW1    = (const float*)d_in[9];
    const float* mb1    = (const float*)d_in[10];
    const float* mang1  = (const float*)d_in[11];
    const float* mgamma = (const float*)d_in[12];
    const float* mbeta  = (const float*)d_in[13];
    const float* mW2    = (const float*)d_in[14];
    // d_in[15] = mb2 (softmax-invariant, unused)
    const float* mang2  = (const float*)d_in[16];
    const float* cc     = (const float*)d_in[17];
    const float* rc     = (const float*)d_in[18];
    const float* ic     = (const float*)d_in[19];
    (void)n_in; (void)out_size;

    int B = in_sizes[0] / (FF * TT * SS);

    // dummy launches so ncu's bounded capture lands on k1
    kalign<<<1, 32>>>();
    kalign<<<1, 32>>>();

    int prepN = TT * 16384 + TT * H1 + 32768 + H2;
    kprep<<<(prepN + 255) / 256, 256>>>(W1, ang1, W2, ang2, mW1, mang1, mW2, mang2);

    dim3 g1(TT, B);
    k1<<<g1, 256>>>(path, b1, gamma1, beta1);
    k2<<<B, 256>>>(mb1, mgamma, mbeta, cc, rc, ic, (float*)d_out);
}